// round 8
// baseline (speedup 1.0000x reference)
#include <cuda_runtime.h>
#include <cuda_bf16.h>
#include <math.h>
#include <stdint.h>

#define BB 64
#define SS 512
#define HH 1024
#define TT 24
#define NROWS (BB*SS)

#define GRID 128
#define NTH 256                    // 8 warps
#define NWARP 8
#define NCHUNK 64                  // K chunks of 16
#define PW 1032                    // W smem pitch in bf16 (conflict-free)

// ---- smem layout (bytes) ----
#define WHI_OFF 0
#define WLO_OFF 49536              // 24*1032*2
#define SB_OFF  99072
#define SRED_OFF (99072+128)
#define SMEM_TOTAL (99072+256)

// ---------------- device scratch ----------------
__device__ float    g_loss_sum;
__device__ unsigned g_ticket;

__device__ __forceinline__ float neg_inf() { return __int_as_float(0xff800000); }

// pack two floats to bf16x2: lower half = x, upper = y
__device__ __forceinline__ uint32_t packbf(float x, float y) {
    uint32_t r; asm("cvt.rn.bf16x2.f32 %0, %1, %2;" : "=r"(r) : "f"(y), "f"(x)); return r;
}
// split float2 into bf16x2 hi + bf16x2 lo(residual)
__device__ __forceinline__ void split2f(float2 v, uint32_t& hi, uint32_t& lo) {
    hi = packbf(v.x, v.y);
    float rx = v.x - __uint_as_float(hi << 16);
    float ry = v.y - __uint_as_float(hi & 0xFFFF0000u);
    lo = packbf(rx, ry);
}

__device__ __forceinline__ void mma16816(float* c, const uint32_t* a, uint32_t b0, uint32_t b1) {
    asm volatile("mma.sync.aligned.m16n8k16.row.col.f32.bf16.bf16.f32 "
        "{%0,%1,%2,%3}, {%4,%5,%6,%7}, {%8,%9}, {%0,%1,%2,%3};"
        : "+f"(c[0]), "+f"(c[1]), "+f"(c[2]), "+f"(c[3])
        : "r"(a[0]), "r"(a[1]), "r"(a[2]), "r"(a[3]), "r"(b0), "r"(b1));
}

__device__ __forceinline__ int getmask(const void* p, int mt, long i) {
    return mt == 0 ? (((const unsigned char*)p)[i] != 0)
         : mt == 1 ? (((const float*)p)[i] != 0.0f)
                   : (((const int*)p)[i] != 0);
}

// ================= single fused kernel =================
__global__ void __launch_bounds__(NTH, 1)
crf_kernel(const float* __restrict__ feats, const float* __restrict__ W,
           const float* __restrict__ bias, const int* __restrict__ target,
           const void* __restrict__ mask_raw, const float* __restrict__ trans,
           float* __restrict__ out, int has_loss) {
    extern __shared__ unsigned char smem[];
    float* sb   = (float*)(smem + SB_OFF);
    float* sred = (float*)(smem + SRED_OFF);
    __shared__ int   s_flag, s_nz;
    __shared__ float s_tot;

    const int tid = threadIdx.x, warp = tid >> 5, lane = tid & 31;
    const int r = lane >> 2, kp = lane & 3;
    float* emis = out + has_loss;    // NOTE: only 4-byte aligned -> scalar stores only!

    // ---- stage + split W into smem [n][k] bf16, pitch PW ----
    for (int i = tid; i < TT * 512; i += NTH) {
        int n = i >> 9, kq = i & 511;
        float2 v = ((const float2*)W)[n * 512 + kq];
        uint32_t hi, lo;
        split2f(v, hi, lo);
        *(uint32_t*)(smem + WHI_OFF + (n * PW + kq * 2) * 2) = hi;
        *(uint32_t*)(smem + WLO_OFF + (n * PW + kq * 2) * 2) = lo;
    }
    if (tid < TT) sb[tid] = bias[tid];
    if (tid < NWARP) sred[tid] = 0.0f;
    if (tid == 0) { s_flag = 0; s_nz = 0; s_tot = 0.0f; }
    __syncthreads();

    const unsigned u0 = *(const unsigned*)mask_raw;
    const int mt_ = (u0 == 0x01010101u) ? 0 : ((u0 == 0x3F800000u) ? 1 : 2);

    const int  tile = blockIdx.x * NWARP + warp;    // 0..1023, exact
    const long row0 = (long)tile * 32;
    const float2* f2g = (const float2*)feats;

    // per-thread global row bases (float2 units)
    const long rb0 = (row0 + r)      * 512 + kp;
    const long rb1 = (row0 + r + 8)  * 512 + kp;
    const long rb2 = (row0 + r + 16) * 512 + kp;
    const long rb3 = (row0 + r + 24) * 512 + kp;

    float acc[2][3][4];
    #pragma unroll
    for (int m = 0; m < 2; m++)
        #pragma unroll
        for (int n = 0; n < 3; n++)
            #pragma unroll
            for (int q = 0; q < 4; q++) acc[m][n][q] = 0.0f;

    float2 fb[2][8];
    // prefetch chunk 0
    {
        fb[0][0] = f2g[rb0];     fb[0][1] = f2g[rb1];
        fb[0][2] = f2g[rb0 + 4]; fb[0][3] = f2g[rb1 + 4];
        fb[0][4] = f2g[rb2];     fb[0][5] = f2g[rb3];
        fb[0][6] = f2g[rb2 + 4]; fb[0][7] = f2g[rb3 + 4];
    }

    const unsigned bq = (unsigned)(r * PW + kp * 2) * 2;   // base byte offset in W rows

    #pragma unroll 1
    for (int ch = 0; ch < NCHUNK; ch++) {
        const int cur = ch & 1;
        if (ch + 1 < NCHUNK) {
            const int c8 = (ch + 1) * 8;
            float2* nb = fb[cur ^ 1];
            nb[0] = f2g[rb0 + c8];     nb[1] = f2g[rb1 + c8];
            nb[2] = f2g[rb0 + c8 + 4]; nb[3] = f2g[rb1 + c8 + 4];
            nb[4] = f2g[rb2 + c8];     nb[5] = f2g[rb3 + c8];
            nb[6] = f2g[rb2 + c8 + 4]; nb[7] = f2g[rb3 + c8 + 4];
        }
        // convert A fragments
        uint32_t ahi[2][4], alo[2][4];
        #pragma unroll
        for (int m = 0; m < 2; m++)
            #pragma unroll
            for (int q = 0; q < 4; q++)
                split2f(fb[cur][m * 4 + q], ahi[m][q], alo[m][q]);

        // B fragments + MMAs
        const unsigned cb = bq + (unsigned)ch * 32;        // + c*16 bf16 = 32 bytes
        #pragma unroll
        for (int nt = 0; nt < 3; nt++) {
            const unsigned o = cb + (unsigned)nt * (8 * PW * 2);
            uint32_t bh0 = *(const uint32_t*)(smem + WHI_OFF + o);
            uint32_t bh1 = *(const uint32_t*)(smem + WHI_OFF + o + 16);
            uint32_t bl0 = *(const uint32_t*)(smem + WLO_OFF + o);
            uint32_t bl1 = *(const uint32_t*)(smem + WLO_OFF + o + 16);
            #pragma unroll
            for (int m = 0; m < 2; m++) {
                mma16816(acc[m][nt], ahi[m], bh0, bh1);
                mma16816(acc[m][nt], ahi[m], bl0, bl1);
                mma16816(acc[m][nt], alo[m], bh0, bh1);
            }
        }
    }

    // ---- epilogue: bias, emission stores (SCALAR: emis only 4B-aligned),
    //      quad-shfl LSE + target, fast-path loss ----
    float contrib = 0.0f;
    #pragma unroll
    for (int m = 0; m < 2; m++) {
        #pragma unroll
        for (int rr = 0; rr < 2; rr++) {
            const long row = row0 + m * 16 + rr * 8 + r;
            float e[6];
            float* eo = emis + row * TT;
            #pragma unroll
            for (int nt = 0; nt < 3; nt++) {
                const int col = nt * 8 + kp * 2;
                e[nt * 2]     = acc[m][nt][rr * 2]     + sb[col];
                e[nt * 2 + 1] = acc[m][nt][rr * 2 + 1] + sb[col + 1];
                eo[col]     = e[nt * 2];
                eo[col + 1] = e[nt * 2 + 1];
            }
            float mx = e[0];
            #pragma unroll
            for (int q = 1; q < 6; q++) mx = fmaxf(mx, e[q]);
            mx = fmaxf(mx, __shfl_xor_sync(0xffffffffu, mx, 1));
            mx = fmaxf(mx, __shfl_xor_sync(0xffffffffu, mx, 2));
            float ex = 0.0f;
            #pragma unroll
            for (int q = 0; q < 6; q++) ex += __expf(e[q] - mx);
            const int tg = target[row];
            float sc = 0.0f;
            #pragma unroll
            for (int nt = 0; nt < 3; nt++) {
                const int col = nt * 8 + kp * 2;
                sc += (tg == col) ? e[nt * 2] : 0.0f;
                sc += (tg == col + 1) ? e[nt * 2 + 1] : 0.0f;
            }
            ex += __shfl_xor_sync(0xffffffffu, ex, 1);
            sc += __shfl_xor_sync(0xffffffffu, sc, 1);
            ex += __shfl_xor_sync(0xffffffffu, ex, 2);
            sc += __shfl_xor_sync(0xffffffffu, sc, 2);
            if (kp == 0) {
                const float lse = mx + __logf(ex);
                const int s  = (int)(row & (SS - 1));
                const int mk = getmask(mask_raw, mt_, row);
                contrib += mk ? (sc - lse) : (s == 0 ? -lse : 0.0f);
            }
        }
    }

    // ---- warp + block reduce, ticket ----
    contrib += __shfl_xor_sync(0xffffffffu, contrib, 16);
    contrib += __shfl_xor_sync(0xffffffffu, contrib, 8);
    contrib += __shfl_xor_sync(0xffffffffu, contrib, 4);
    contrib += __shfl_xor_sync(0xffffffffu, contrib, 2);
    contrib += __shfl_xor_sync(0xffffffffu, contrib, 1);
    if (lane == 0) sred[warp] = contrib;
    __syncthreads();
    if (tid == 0) {
        float part = 0.0f;
        #pragma unroll
        for (int w = 0; w < NWARP; w++) part += sred[w];
        atomicAdd(&g_loss_sum, part);
        __threadfence();
        unsigned tk = atomicAdd(&g_ticket, 1u);
        s_flag = (tk == GRID - 1);
    }
    __syncthreads();
    if (!s_flag) return;

    // ================= last block: finalize =================
    float* st = (float*)smem;          // transition [576] (W area reusable now)
    float* sp = st + 576;              // per-warp scan state [8][24]
    {
        int lnz = 0;
        for (int i = tid; i < TT * TT; i += NTH) {
            float v = trans[i];
            st[i] = v;
            lnz |= (v != 0.0f);
        }
        if (lnz) atomicOr(&s_nz, 1);
    }
    __syncthreads();

    if (!s_nz) {
        if (tid == 0) {
            if (has_loss) out[0] = -g_loss_sum / (float)BB;
            g_loss_sum = 0.0f;
            g_ticket = 0u;
        }
        return;
    }

    // generic nonzero-transition path (not taken for this dataset)
    {
        float wsum = 0.0f;
        float* msp = sp + warp * TT;
        for (int b = warp; b < BB; b += NWARP) {
            float sum = 0.0f;
            for (int s = lane; s < SS; s += 32) {
                const long idx = (long)b * SS + s;
                if (getmask(mask_raw, mt_, idx)) {
                    float v = emis[idx * TT + target[idx]];
                    if (s > 0) v += st[target[idx - 1] * TT + target[idx]];
                    sum += v;
                }
            }
            sum += __shfl_xor_sync(0xffffffffu, sum, 16);
            sum += __shfl_xor_sync(0xffffffffu, sum, 8);
            sum += __shfl_xor_sync(0xffffffffu, sum, 4);
            sum += __shfl_xor_sync(0xffffffffu, sum, 2);
            sum += __shfl_xor_sync(0xffffffffu, sum, 1);

            if (lane < TT) msp[lane] = emis[(long)b * SS * TT + lane];
            __syncwarp();
            for (int s = 1; s < SS; s++) {
                if (getmask(mask_raw, mt_, (long)b * SS + s)) {
                    float nv = 0.0f;
                    if (lane < TT) {
                        float mm = neg_inf();
                        #pragma unroll
                        for (int j = 0; j < TT; j++) mm = fmaxf(mm, msp[j] + st[j * TT + lane]);
                        float a = 0.0f;
                        #pragma unroll
                        for (int j = 0; j < TT; j++) a += __expf(msp[j] + st[j * TT + lane] - mm);
                        nv = emis[((long)b * SS + s) * TT + lane] + mm + __logf(a);
                    }
                    __syncwarp();
                    if (lane < TT) msp[lane] = nv;
                    __syncwarp();
                }
            }
            float e2 = (lane < TT) ? msp[lane] : neg_inf();
            float mm = e2;
            mm = fmaxf(mm, __shfl_xor_sync(0xffffffffu, mm, 16));
            mm = fmaxf(mm, __shfl_xor_sync(0xffffffffu, mm, 8));
            mm = fmaxf(mm, __shfl_xor_sync(0xffffffffu, mm, 4));
            mm = fmaxf(mm, __shfl_xor_sync(0xffffffffu, mm, 2));
            mm = fmaxf(mm, __shfl_xor_sync(0xffffffffu, mm, 1));
            float ex2 = (lane < TT) ? __expf(e2 - mm) : 0.0f;
            ex2 += __shfl_xor_sync(0xffffffffu, ex2, 16);
            ex2 += __shfl_xor_sync(0xffffffffu, ex2, 8);
            ex2 += __shfl_xor_sync(0xffffffffu, ex2, 4);
            ex2 += __shfl_xor_sync(0xffffffffu, ex2, 2);
            ex2 += __shfl_xor_sync(0xffffffffu, ex2, 1);
            if (lane == 0) wsum += sum - (mm + __logf(ex2));
        }
        if (lane == 0) atomicAdd(&s_tot, wsum);
    }
    __syncthreads();
    if (tid == 0) {
        if (has_loss) out[0] = -s_tot / (float)BB;
        g_loss_sum = 0.0f;
        g_ticket = 0u;
    }
}

// ---------------- launch ----------------
extern "C" void kernel_launch(void* const* d_in, const int* in_sizes, int n_in,
                              void* d_out, int out_size) {
    const float* feats  = (const float*)d_in[0];   // (B,S,H)
    const int*   target = (const int*)d_in[1];     // (B,S)
    const void*  mask   = d_in[2];                 // (B,S) dtype auto-detected
    const float* W      = (const float*)d_in[3];   // (T,H)
    const float* bias   = (const float*)d_in[4];   // (T,)
    const float* trans  = (const float*)d_in[5];   // (T,T)

    float* out = (float*)d_out;
    const int has_loss = (out_size == NROWS * TT + 1) ? 1 : 0;

    static int attr_set = 0;
    if (!attr_set) {
        cudaFuncSetAttribute(crf_kernel, cudaFuncAttributeMaxDynamicSharedMemorySize, SMEM_TOTAL);
        attr_set = 1;
    }

    crf_kernel<<<GRID, NTH, SMEM_TOTAL>>>(feats, W, bias, target, mask, trans, out, has_loss);
}

// round 9
// speedup vs baseline: 2.0509x; 2.0509x over previous
#include <cuda_runtime.h>
#include <cuda_bf16.h>
#include <math.h>
#include <stdint.h>

#define BB 64
#define SS 512
#define HH 1024
#define TT 24
#define NROWS (BB*SS)

#define GRID 148
#define NTH 512                    // 16 warps
#define NWARP 16
#define NCHUNK 64                  // K chunks of 16
#define NTILES (NROWS/16)          // 2048 tiles of 16 rows
#define PW 1032                    // W smem pitch in bf16 (conflict-free)

// ---- smem layout (bytes) ----
#define WHI_OFF 0
#define WLO_OFF 49536              // 24*1032*2
#define SB_OFF  99072
#define SRED_OFF (99072+128)
#define SMEM_TOTAL (99072+256)

// ---------------- device scratch ----------------
__device__ float    g_loss_sum;
__device__ unsigned g_ticket;
__device__ unsigned g_tile;

__device__ __forceinline__ float neg_inf() { return __int_as_float(0xff800000); }

// pack two floats to bf16x2: lower half = x, upper = y
__device__ __forceinline__ uint32_t packbf(float x, float y) {
    uint32_t r; asm("cvt.rn.bf16x2.f32 %0, %1, %2;" : "=r"(r) : "f"(y), "f"(x)); return r;
}
// split (x,y) into bf16x2 hi + bf16x2 lo(residual)
__device__ __forceinline__ void split2f(float x, float y, uint32_t& hi, uint32_t& lo) {
    hi = packbf(x, y);
    float rx = x - __uint_as_float(hi << 16);
    float ry = y - __uint_as_float(hi & 0xFFFF0000u);
    lo = packbf(rx, ry);
}

__device__ __forceinline__ void mma16816(float* c, const uint32_t* a, uint32_t b0, uint32_t b1) {
    asm volatile("mma.sync.aligned.m16n8k16.row.col.f32.bf16.bf16.f32 "
        "{%0,%1,%2,%3}, {%4,%5,%6,%7}, {%8,%9}, {%0,%1,%2,%3};"
        : "+f"(c[0]), "+f"(c[1]), "+f"(c[2]), "+f"(c[3])
        : "r"(a[0]), "r"(a[1]), "r"(a[2]), "r"(a[3]), "r"(b0), "r"(b1));
}

__device__ __forceinline__ int getmask(const void* p, int mt, long i) {
    return mt == 0 ? (((const unsigned char*)p)[i] != 0)
         : mt == 1 ? (((const float*)p)[i] != 0.0f)
                   : (((const int*)p)[i] != 0);
}

// ================= single fused persistent kernel =================
__global__ void __launch_bounds__(NTH, 1)
crf_kernel(const float* __restrict__ feats, const float* __restrict__ W,
           const float* __restrict__ bias, const int* __restrict__ target,
           const void* __restrict__ mask_raw, const float* __restrict__ trans,
           float* __restrict__ out, int has_loss) {
    extern __shared__ unsigned char smem[];
    float* sb   = (float*)(smem + SB_OFF);
    float* sred = (float*)(smem + SRED_OFF);
    __shared__ int   s_flag, s_nz;
    __shared__ float s_tot;

    const int tid = threadIdx.x, warp = tid >> 5, lane = tid & 31;
    const int r = lane >> 2, kp = lane & 3;
    float* emis = out + has_loss;    // 4B-aligned only: scalar stores

    // ---- stage + split W with in-chunk k-permutation ----
    // logical k 4q..4q+3 of chunk c  ->  HW slots (2q,2q+1) and (8+2q,8+2q+1)
    for (int i = tid; i < TT * 256; i += NTH) {
        int n = i >> 8, f4i = i & 255;
        int c = f4i >> 2, q = f4i & 3;
        float4 v = ((const float4*)W)[n * 256 + f4i];
        uint32_t h0, l0, h1, l1;
        split2f(v.x, v.y, h0, l0);
        split2f(v.z, v.w, h1, l1);
        unsigned base = (unsigned)(n * PW + c * 16) * 2;   // bytes
        *(uint32_t*)(smem + WHI_OFF + base + q * 4)      = h0;
        *(uint32_t*)(smem + WHI_OFF + base + 16 + q * 4) = h1;
        *(uint32_t*)(smem + WLO_OFF + base + q * 4)      = l0;
        *(uint32_t*)(smem + WLO_OFF + base + 16 + q * 4) = l1;
    }
    if (tid < TT) sb[tid] = bias[tid];
    if (tid < NWARP) sred[tid] = 0.0f;
    if (tid == 0) { s_flag = 0; s_nz = 0; s_tot = 0.0f; }
    __syncthreads();

    const unsigned u0 = *(const unsigned*)mask_raw;
    const int mt_ = (u0 == 0x01010101u) ? 0 : ((u0 == 0x3F800000u) ? 1 : 2);

    const float4* f4g = (const float4*)feats;
    const unsigned bq = (unsigned)(r * PW + kp * 2) * 2;   // B frag base byte offset
    float contrib = 0.0f;

    // ---- per-warp 16-row tile steal loop ----
    for (;;) {
        unsigned tile;
        if (lane == 0) tile = atomicAdd(&g_tile, 1u);
        tile = __shfl_sync(0xffffffffu, tile, 0);
        if (tile >= NTILES) break;
        const long row0 = (long)tile * 16;

        const long ra = (row0 + r)     * 256 + kp;   // float4 units
        const long rb = (row0 + r + 8) * 256 + kp;

        float acc[3][4];
        #pragma unroll
        for (int nt = 0; nt < 3; nt++)
            #pragma unroll
            for (int q = 0; q < 4; q++) acc[nt][q] = 0.0f;

        float4 fb0[2], fb1[2], fb2[2], fb3[2];
        fb0[0] = f4g[ra];      fb0[1] = f4g[rb];
        fb1[0] = f4g[ra + 4];  fb1[1] = f4g[rb + 4];
        fb2[0] = f4g[ra + 8];  fb2[1] = f4g[rb + 8];

        #define LOADC(buf, c) do { \
            int _nc = (c) < NCHUNK ? (c) : (NCHUNK - 1); \
            buf[0] = f4g[ra + _nc * 4]; buf[1] = f4g[rb + _nc * 4]; \
        } while (0)

        #define COMPUTE(buf, ch) do { \
            uint32_t ahi[4], alo[4]; \
            split2f(buf[0].x, buf[0].y, ahi[0], alo[0]); \
            split2f(buf[1].x, buf[1].y, ahi[1], alo[1]); \
            split2f(buf[0].z, buf[0].w, ahi[2], alo[2]); \
            split2f(buf[1].z, buf[1].w, ahi[3], alo[3]); \
            const unsigned cb = bq + (unsigned)(ch) * 32; \
            _Pragma("unroll") \
            for (int nt = 0; nt < 3; nt++) { \
                const unsigned o = cb + (unsigned)nt * (8 * PW * 2); \
                uint32_t bh0 = *(const uint32_t*)(smem + WHI_OFF + o); \
                uint32_t bh1 = *(const uint32_t*)(smem + WHI_OFF + o + 16); \
                uint32_t bl0 = *(const uint32_t*)(smem + WLO_OFF + o); \
                uint32_t bl1 = *(const uint32_t*)(smem + WLO_OFF + o + 16); \
                mma16816(acc[nt], ahi, bh0, bh1); \
                mma16816(acc[nt], ahi, bl0, bl1); \
                mma16816(acc[nt], alo, bh0, bh1); \
            } \
        } while (0)

        #pragma unroll 1
        for (int c = 0; c < NCHUNK; c += 4) {
            LOADC(fb3, c + 3); COMPUTE(fb0, c);
            LOADC(fb0, c + 4); COMPUTE(fb1, c + 1);
            LOADC(fb1, c + 5); COMPUTE(fb2, c + 2);
            LOADC(fb2, c + 6); COMPUTE(fb3, c + 3);
        }
        #undef LOADC
        #undef COMPUTE

        // ---- epilogue: bias, scalar emission stores, quad-shfl LSE + target ----
        #pragma unroll
        for (int rr = 0; rr < 2; rr++) {
            const long row = row0 + rr * 8 + r;
            float e[6];
            float* eo = emis + row * TT;
            #pragma unroll
            for (int nt = 0; nt < 3; nt++) {
                const int col = nt * 8 + kp * 2;
                e[nt * 2]     = acc[nt][rr * 2]     + sb[col];
                e[nt * 2 + 1] = acc[nt][rr * 2 + 1] + sb[col + 1];
                eo[col]     = e[nt * 2];
                eo[col + 1] = e[nt * 2 + 1];
            }
            float mx = e[0];
            #pragma unroll
            for (int q = 1; q < 6; q++) mx = fmaxf(mx, e[q]);
            mx = fmaxf(mx, __shfl_xor_sync(0xffffffffu, mx, 1));
            mx = fmaxf(mx, __shfl_xor_sync(0xffffffffu, mx, 2));
            float ex = 0.0f;
            #pragma unroll
            for (int q = 0; q < 6; q++) ex += __expf(e[q] - mx);
            const int tg = target[row];
            float sc = 0.0f;
            #pragma unroll
            for (int nt = 0; nt < 3; nt++) {
                const int col = nt * 8 + kp * 2;
                sc += (tg == col) ? e[nt * 2] : 0.0f;
                sc += (tg == col + 1) ? e[nt * 2 + 1] : 0.0f;
            }
            ex += __shfl_xor_sync(0xffffffffu, ex, 1);
            sc += __shfl_xor_sync(0xffffffffu, sc, 1);
            ex += __shfl_xor_sync(0xffffffffu, ex, 2);
            sc += __shfl_xor_sync(0xffffffffu, sc, 2);
            if (kp == 0) {
                const float lse = mx + __logf(ex);
                const int s  = (int)(row & (SS - 1));
                const int mk = getmask(mask_raw, mt_, row);
                contrib += mk ? (sc - lse) : (s == 0 ? -lse : 0.0f);
            }
        }
    }

    // ---- warp + block reduce, ticket ----
    contrib += __shfl_xor_sync(0xffffffffu, contrib, 16);
    contrib += __shfl_xor_sync(0xffffffffu, contrib, 8);
    contrib += __shfl_xor_sync(0xffffffffu, contrib, 4);
    contrib += __shfl_xor_sync(0xffffffffu, contrib, 2);
    contrib += __shfl_xor_sync(0xffffffffu, contrib, 1);
    if (lane == 0) sred[warp] = contrib;
    __syncthreads();
    if (tid == 0) {
        float part = 0.0f;
        #pragma unroll
        for (int w = 0; w < NWARP; w++) part += sred[w];
        atomicAdd(&g_loss_sum, part);
        __threadfence();
        unsigned tk = atomicAdd(&g_ticket, 1u);
        s_flag = (tk == GRID - 1);
    }
    __syncthreads();
    if (!s_flag) return;

    // ================= last block: finalize =================
    float* st = (float*)smem;          // transition [576] (W area reusable now)
    float* sp = st + 576;              // per-warp scan state [16][24]
    {
        int lnz = 0;
        for (int i = tid; i < TT * TT; i += NTH) {
            float v = trans[i];
            st[i] = v;
            lnz |= (v != 0.0f);
        }
        if (lnz) atomicOr(&s_nz, 1);
    }
    __syncthreads();

    if (!s_nz) {
        if (tid == 0) {
            if (has_loss) out[0] = -g_loss_sum / (float)BB;
            g_loss_sum = 0.0f;
            g_ticket = 0u;
            g_tile = 0u;
        }
        return;
    }

    // generic nonzero-transition path (not taken for this dataset)
    {
        float wsum = 0.0f;
        float* msp = sp + warp * TT;
        for (int b = warp; b < BB; b += NWARP) {
            float sum = 0.0f;
            for (int s = lane; s < SS; s += 32) {
                const long idx = (long)b * SS + s;
                if (getmask(mask_raw, mt_, idx)) {
                    float v = emis[idx * TT + target[idx]];
                    if (s > 0) v += st[target[idx - 1] * TT + target[idx]];
                    sum += v;
                }
            }
            sum += __shfl_xor_sync(0xffffffffu, sum, 16);
            sum += __shfl_xor_sync(0xffffffffu, sum, 8);
            sum += __shfl_xor_sync(0xffffffffu, sum, 4);
            sum += __shfl_xor_sync(0xffffffffu, sum, 2);
            sum += __shfl_xor_sync(0xffffffffu, sum, 1);

            if (lane < TT) msp[lane] = emis[(long)b * SS * TT + lane];
            __syncwarp();
            for (int s = 1; s < SS; s++) {
                if (getmask(mask_raw, mt_, (long)b * SS + s)) {
                    float nv = 0.0f;
                    if (lane < TT) {
                        float mm = neg_inf();
                        #pragma unroll
                        for (int j = 0; j < TT; j++) mm = fmaxf(mm, msp[j] + st[j * TT + lane]);
                        float a = 0.0f;
                        #pragma unroll
                        for (int j = 0; j < TT; j++) a += __expf(msp[j] + st[j * TT + lane] - mm);
                        nv = emis[((long)b * SS + s) * TT + lane] + mm + __logf(a);
                    }
                    __syncwarp();
                    if (lane < TT) msp[lane] = nv;
                    __syncwarp();
                }
            }
            float e2 = (lane < TT) ? msp[lane] : neg_inf();
            float mm = e2;
            mm = fmaxf(mm, __shfl_xor_sync(0xffffffffu, mm, 16));
            mm = fmaxf(mm, __shfl_xor_sync(0xffffffffu, mm, 8));
            mm = fmaxf(mm, __shfl_xor_sync(0xffffffffu, mm, 4));
            mm = fmaxf(mm, __shfl_xor_sync(0xffffffffu, mm, 2));
            mm = fmaxf(mm, __shfl_xor_sync(0xffffffffu, mm, 1));
            float ex2 = (lane < TT) ? __expf(e2 - mm) : 0.0f;
            ex2 += __shfl_xor_sync(0xffffffffu, ex2, 16);
            ex2 += __shfl_xor_sync(0xffffffffu, ex2, 8);
            ex2 += __shfl_xor_sync(0xffffffffu, ex2, 4);
            ex2 += __shfl_xor_sync(0xffffffffu, ex2, 2);
            ex2 += __shfl_xor_sync(0xffffffffu, ex2, 1);
            if (lane == 0) wsum += sum - (mm + __logf(ex2));
        }
        if (lane == 0) atomicAdd(&s_tot, wsum);
    }
    __syncthreads();
    if (tid == 0) {
        if (has_loss) out[0] = -s_tot / (float)BB;
        g_loss_sum = 0.0f;
        g_ticket = 0u;
        g_tile = 0u;
    }
}

// ---------------- launch ----------------
extern "C" void kernel_launch(void* const* d_in, const int* in_sizes, int n_in,
                              void* d_out, int out_size) {
    const float* feats  = (const float*)d_in[0];   // (B,S,H)
    const int*   target = (const int*)d_in[1];     // (B,S)
    const void*  mask   = d_in[2];                 // (B,S) dtype auto-detected
    const float* W      = (const float*)d_in[3];   // (T,H)
    const float* bias   = (const float*)d_in[4];   // (T,)
    const float* trans  = (const float*)d_in[5];   // (T,T)

    float* out = (float*)d_out;
    const int has_loss = (out_size == NROWS * TT + 1) ? 1 : 0;

    static int attr_set = 0;
    if (!attr_set) {
        cudaFuncSetAttribute(crf_kernel, cudaFuncAttributeMaxDynamicSharedMemorySize, SMEM_TOTAL);
        attr_set = 1;
    }

    crf_kernel<<<GRID, NTH, SMEM_TOTAL>>>(feats, W, bias, target, mask, trans, out, has_loss);
}